// round 1
// baseline (speedup 1.0000x reference)
#include <cuda_runtime.h>

// Closed-form evaluation of the 20-qubit, depth-2 hardware-efficient circuit.
//
// feature_q = -<Z_q> where
//   <Z_q> = c2_q*c1_q*cx_q - s2_q*s1_q*cx_q * (c1_{q-1}*cx_{q-1}) * (c1_{q+1}*cx_{q+1})
// with cx_j = cos(x_j), c1/s1 = cos/sin(theta[0][j]), c2/s2 = cos/sin(theta[1][j]).
// Boundary neighbor factors are 1. Final CZ layer commutes with Z_q (no effect).
// logits = feature @ W^T + b.

#define N_QUBITS 20

__global__ void quantum_classifier_closed_form(
    const float* __restrict__ x,      // (32, 20)
    const float* __restrict__ theta,  // (2, 20)
    const float* __restrict__ W,      // (2, 20)
    const float* __restrict__ b,      // (2,)
    float* __restrict__ out)          // (32, 2)
{
    const int bi = threadIdx.x;  // batch index, 0..31

    // Per-qubit circuit parameters (uniform across batch) — compute in registers.
    float c1[N_QUBITS], s1[N_QUBITS], c2[N_QUBITS], s2[N_QUBITS];
#pragma unroll
    for (int q = 0; q < N_QUBITS; ++q) {
        __sincosf(theta[q],            &s1[q], &c1[q]);   // theta[0][q]
        __sincosf(theta[N_QUBITS + q], &s2[q], &c2[q]);   // theta[1][q]
    }

    // Data encoding: cos(x_q) per qubit for this batch element.
    float cx[N_QUBITS];
#pragma unroll
    for (int q = 0; q < N_QUBITS; ++q)
        cx[q] = __cosf(x[bi * N_QUBITS + q]);

    float acc0 = b[0];
    float acc1 = b[1];
#pragma unroll
    for (int q = 0; q < N_QUBITS; ++q) {
        float left  = (q > 0)            ? c1[q - 1] * cx[q - 1] : 1.0f;
        float right = (q < N_QUBITS - 1) ? c1[q + 1] * cx[q + 1] : 1.0f;
        float z = c2[q] * c1[q] * cx[q]
                - s2[q] * s1[q] * cx[q] * left * right;
        float f = -z;  // feature_q = 2*P(1) - 1 = -<Z_q>
        acc0 = fmaf(f, W[q],            acc0);
        acc1 = fmaf(f, W[N_QUBITS + q], acc1);
    }

    out[bi * 2 + 0] = acc0;
    out[bi * 2 + 1] = acc1;
}

extern "C" void kernel_launch(void* const* d_in, const int* in_sizes, int n_in,
                              void* d_out, int out_size) {
    const float* x     = (const float*)d_in[0];  // (32, 20)
    const float* theta = (const float*)d_in[1];  // (2, 20)
    const float* W     = (const float*)d_in[2];  // (2, 20)
    const float* b     = (const float*)d_in[3];  // (2,)
    float* out = (float*)d_out;                  // (32, 2)

    quantum_classifier_closed_form<<<1, 32>>>(x, theta, W, b, out);
}